// round 5
// baseline (speedup 1.0000x reference)
#include <cuda_runtime.h>
#include <cuda_bf16.h>
#include <math.h>
#include <stdint.h>

// ---------------- problem constants ----------------
#define BATCH   32
#define SEQ     1000
#define DMODEL  256
#define PATCHSZ 160
#define NLAYERS 6
#define G3      768   // 3*DMODEL

// ---------------- scratch (device globals; no allocs allowed) ----------------
__device__ float g_x [BATCH * SEQ * DMODEL];   // residual stream x
__device__ float g_ln[BATCH * SEQ * DMODEL];   // layernorm(x) per layer
__device__ float g_xp[BATCH * SEQ * G3];       // input projection per layer
__device__ float g_emb[BATCH * DMODEL];        // pooled embedding
__device__ float g_part[BATCH * 25 * DMODEL];  // final-LN partial sums

__device__ __forceinline__ float gelu_exact(float v) {
    return 0.5f * v * (1.0f + erff(v * 0.70710678118654752440f));
}

// fast, accurate-enough (ex2-based, ~1e-6 rel) sigmoid / tanh
__device__ __forceinline__ float fsigmoid(float v) {
    return __fdividef(1.0f, 1.0f + __expf(-v));
}
__device__ __forceinline__ float ftanh(float v) {
    // 1 - 2/(e^{2v}+1); saturates correctly at +/-1 via inf/0 behavior
    return 1.0f - __fdividef(2.0f, __expf(2.0f * v) + 1.0f);
}

// =====================================================================
// Kernel 1: patchify conv (k=stride=160) + exact GELU + pos emb -> g_x
// =====================================================================
__global__ __launch_bounds__(256) void k_conv(const float* __restrict__ wave,
                                              const float* __restrict__ cw,
                                              const float* __restrict__ pos) {
    __shared__ __align__(16) float sw[64 * PATCHSZ];   // 40 KB
    const int tid = threadIdx.x;
    const long base = (long)blockIdx.x * 64 * PATCHSZ;

    const float4* src = (const float4*)(wave + base);
    float4* dst = (float4*)sw;
#pragma unroll
    for (int i = 0; i < 10; i++) dst[tid + i * 256] = src[tid + i * 256];

    float creg[PATCHSZ];
#pragma unroll
    for (int p = 0; p < PATCHSZ; p++) creg[p] = cw[p * DMODEL + tid];
    __syncthreads();

    const int row0 = blockIdx.x * 64;
    for (int r = 0; r < 64; r++) {
        const float4* wv = (const float4*)(sw + r * PATCHSZ);
        float acc = 0.0f;
#pragma unroll
        for (int i = 0; i < PATCHSZ / 4; i++) {
            float4 v = wv[i];
            acc += v.x * creg[4 * i + 0];
            acc += v.y * creg[4 * i + 1];
            acc += v.z * creg[4 * i + 2];
            acc += v.w * creg[4 * i + 3];
        }
        const int row = row0 + r;
        const int s = row % SEQ;
        g_x[(long)row * DMODEL + tid] = gelu_exact(acc) + pos[s * DMODEL + tid];
    }
}

// =====================================================================
// Kernel 2: layernorm over last dim (256). one warp per row.
// =====================================================================
__global__ __launch_bounds__(256) void k_ln(const float* __restrict__ sc,
                                            const float* __restrict__ bi) {
    const int wid = threadIdx.x >> 5, lane = threadIdx.x & 31;
    const long row = (long)blockIdx.x * 8 + wid;
    const float4* xr = (const float4*)(g_x + row * DMODEL);
    float4 v0 = xr[lane];
    float4 v1 = xr[lane + 32];
    float s1 = v0.x + v0.y + v0.z + v0.w + v1.x + v1.y + v1.z + v1.w;
    float s2 = v0.x * v0.x + v0.y * v0.y + v0.z * v0.z + v0.w * v0.w
             + v1.x * v1.x + v1.y * v1.y + v1.z * v1.z + v1.w * v1.w;
#pragma unroll
    for (int o = 16; o > 0; o >>= 1) {
        s1 += __shfl_xor_sync(0xffffffffu, s1, o);
        s2 += __shfl_xor_sync(0xffffffffu, s2, o);
    }
    const float mu  = s1 * (1.0f / 256.0f);
    const float var = s2 * (1.0f / 256.0f) - mu * mu;
    const float inv = rsqrtf(var + 1e-5f);

    const int d0 = lane * 4, d1 = 128 + lane * 4;
    float4 sa = *(const float4*)(sc + d0), sb = *(const float4*)(sc + d1);
    float4 ba = *(const float4*)(bi + d0), bb = *(const float4*)(bi + d1);
    float4 o0, o1;
    o0.x = (v0.x - mu) * inv * sa.x + ba.x;  o0.y = (v0.y - mu) * inv * sa.y + ba.y;
    o0.z = (v0.z - mu) * inv * sa.z + ba.z;  o0.w = (v0.w - mu) * inv * sa.w + ba.w;
    o1.x = (v1.x - mu) * inv * sb.x + bb.x;  o1.y = (v1.y - mu) * inv * sb.y + bb.y;
    o1.z = (v1.z - mu) * inv * sb.z + bb.z;  o1.w = (v1.w - mu) * inv * sb.w + bb.w;
    float4* outr = (float4*)(g_ln + row * DMODEL);
    outr[lane] = o0;
    outr[lane + 32] = o1;
}

// =====================================================================
// Kernel 3: xp = g_ln[32000,256] @ W_ih^T[256,768] + b_ih -> g_xp
// =====================================================================
__global__ __launch_bounds__(256) void k_gemm_xp(const float* __restrict__ W,
                                                 const float* __restrict__ bias) {
    __shared__ __align__(16) float As[128][36];   // [row][k] padded
    __shared__ __align__(16) float Bs[32][132];   // [k][col] padded (transposed)
    const int tid = threadIdx.x;
    const int tx = tid & 15, ty = tid >> 4;
    const int row0 = blockIdx.x * 128, col0 = blockIdx.y * 128;

    float acc[8][8];
#pragma unroll
    for (int i = 0; i < 8; i++)
#pragma unroll
        for (int j = 0; j < 8; j++) acc[i][j] = 0.0f;

    for (int k0 = 0; k0 < DMODEL; k0 += 32) {
#pragma unroll
        for (int it = 0; it < 4; it++) {
            int m = tid + it * 256;
            int r = m >> 3, kq = (m & 7) * 4;
            float4 v = *(const float4*)(g_ln + (long)(row0 + r) * DMODEL + k0 + kq);
            *(float4*)&As[r][kq] = v;
        }
#pragma unroll
        for (int it = 0; it < 4; it++) {
            int m = tid + it * 256;
            int cc = m >> 3, kq = (m & 7) * 4;
            float4 v = *(const float4*)(W + (long)(col0 + cc) * DMODEL + k0 + kq);
            Bs[kq + 0][cc] = v.x; Bs[kq + 1][cc] = v.y;
            Bs[kq + 2][cc] = v.z; Bs[kq + 3][cc] = v.w;
        }
        __syncthreads();
#pragma unroll
        for (int kk = 0; kk < 32; kk++) {
            float a[8], b[8];
#pragma unroll
            for (int i = 0; i < 8; i++) a[i] = As[ty * 8 + i][kk];
            float4 b0 = *(float4*)&Bs[kk][tx * 8];
            float4 b1 = *(float4*)&Bs[kk][tx * 8 + 4];
            b[0] = b0.x; b[1] = b0.y; b[2] = b0.z; b[3] = b0.w;
            b[4] = b1.x; b[5] = b1.y; b[6] = b1.z; b[7] = b1.w;
#pragma unroll
            for (int i = 0; i < 8; i++)
#pragma unroll
                for (int j = 0; j < 8; j++) acc[i][j] += a[i] * b[j];
        }
        __syncthreads();
    }
#pragma unroll
    for (int i = 0; i < 8; i++) {
        const long row = row0 + ty * 8 + i;
        const int col = col0 + tx * 8;
        float4 o0, o1;
        o0.x = acc[i][0] + bias[col + 0]; o0.y = acc[i][1] + bias[col + 1];
        o0.z = acc[i][2] + bias[col + 2]; o0.w = acc[i][3] + bias[col + 3];
        o1.x = acc[i][4] + bias[col + 4]; o1.y = acc[i][5] + bias[col + 5];
        o1.z = acc[i][6] + bias[col + 6]; o1.w = acc[i][7] + bias[col + 7];
        *(float4*)(g_xp + row * G3 + col)     = o0;
        *(float4*)(g_xp + row * G3 + col + 4) = o1;
    }
}

// =====================================================================
// Kernel 4: GRU recurrence. cluster(4) per batch element, grid (4,32),
// block 384, weights register-resident as f32x2 pairs (FFMA2 matvec).
// h TRIPLE-buffered in SMEM; per-step sync via DSMEM stores +
// mbarrier.arrive.release.cluster (no barrier.cluster in the loop).
// Triple buffering makes producer->consumer WAR safe without empty bars:
// overwrite of buf t%3 (for step t+3) happens-after full[t+2], which
// happens-after every CTA's reads of buf t%3 at step t.
// =====================================================================
__global__ void __cluster_dims__(4, 1, 1) __launch_bounds__(384, 1)
k_gru(const float* __restrict__ whh, const float* __restrict__ bhh) {
    __shared__ __align__(16) float h_buf[3][DMODEL];
    __shared__ float s_sums[192];
    __shared__ __align__(8) unsigned long long s_bar[3];

    const int c   = blockIdx.x;          // cluster rank 0..3
    const int b   = blockIdx.y;
    const int tid = threadIdx.x;
    const int w   = tid >> 5, l = tid & 31;
    const int o   = w * 16 + (l & 15);   // 0..191: CTA-local output index
    const int kh  = l >> 4;              // k half
    const int gg  = o >> 6, dd = o & 63;
    const int R   = gg * DMODEL + c * 64 + dd;   // gate row in [0,768)

    // weight slice: 128 floats = 64 f32x2 pairs in registers
    unsigned long long wreg[64];
    {
        const ulonglong2* wp = (const ulonglong2*)(whh + (long)R * DMODEL + kh * 128);
#pragma unroll
        for (int i = 0; i < 32; i++) { ulonglong2 t2 = wp[i]; wreg[2*i] = t2.x; wreg[2*i+1] = t2.y; }
    }
    const float breg = (kh == 0) ? bhh[R] : 0.0f;

    // init h buffers + mbarriers (count = 64 writers x 4 CTAs = 256/phase)
    for (int i = tid; i < 3 * DMODEL; i += 384) ((float*)h_buf)[i] = 0.0f;
    if (tid == 0) {
#pragma unroll
        for (int m = 0; m < 3; m++) {
            uint32_t ba = (uint32_t)__cvta_generic_to_shared(&s_bar[m]);
            asm volatile("mbarrier.init.shared.b64 [%0], %1;" :: "r"(ba), "r"(256u) : "memory");
        }
    }
    __syncthreads();

    const uint32_t bar_loc = (uint32_t)__cvta_generic_to_shared(&s_bar[0]);
    const uint32_t h_loc   = (uint32_t)__cvta_generic_to_shared(&h_buf[0][c * 64 + (tid & 63)]);

    const float* xpb = g_xp + (long)b * SEQ * G3;
    float* xb = g_x + (long)b * SEQ * DMODEL;
    const int d = c * 64 + tid;          // gate threads: tid < 64

    float pxr = 0.f, pxz = 0.f, pxn = 0.f, pxv = 0.f;
    if (tid < 64) {
        pxr = xpb[d]; pxz = xpb[256 + d]; pxn = xpb[512 + d];
        pxv = xb[c * 64 + tid];
    }
    // all mbarriers initialized cluster-wide before any arrive
    asm volatile("barrier.cluster.arrive.aligned;\n\tbarrier.cluster.wait.aligned;" ::: "memory");

    unsigned ph0 = 0, ph1 = 0, ph2 = 0;
    int m = 0;                            // t % 3
    for (int t = 0; t < SEQ; t++) {
        if (t) {
            const uint32_t mb = bar_loc + m * 8;
            const unsigned par = (m == 0) ? ph0 : ((m == 1) ? ph1 : ph2);
            unsigned done;
            asm volatile(
                "{\n\t.reg .pred p;\n\t"
                "mbarrier.try_wait.parity.acquire.cluster.shared::cta.b64 p, [%1], %2;\n\t"
                "selp.b32 %0, 1, 0, p;\n\t}"
                : "=r"(done) : "r"(mb), "r"(par) : "memory");
            if (!done) {
                asm volatile(
                    "{\n\t.reg .pred P1;\n\t"
                    "WL%=:\n\t"
                    "mbarrier.try_wait.parity.acquire.cluster.shared::cta.b64 P1, [%0], %1, 0x989680;\n\t"
                    "@P1 bra.uni WD%=;\n\t"
                    "bra.uni WL%=;\n\t"
                    "WD%=:\n\t}"
                    :: "r"(mb), "r"(par) : "memory");
            }
            if (m == 0) ph0 ^= 1u; else if (m == 1) ph1 ^= 1u; else ph2 ^= 1u;
        }

        // ---- matvec: 64 packed FFMA2 against h_buf[m] ----
        unsigned long long acc2;
        asm("mov.b64 %0, {%1, %2};" : "=l"(acc2) : "f"(breg), "f"(0.0f));
        const ulonglong2* hv = (const ulonglong2*)&h_buf[m][kh * 128];
#pragma unroll
        for (int i = 0; i < 32; i++) {
            ulonglong2 h2 = hv[i];
            asm("fma.rn.f32x2 %0, %1, %2, %3;" : "=l"(acc2) : "l"(wreg[2*i]),   "l"(h2.x), "l"(acc2));
            asm("fma.rn.f32x2 %0, %1, %2, %3;" : "=l"(acc2) : "l"(wreg[2*i+1]), "l"(h2.y), "l"(acc2));
        }
        float alo, ahi;
        asm("mov.b64 {%0, %1}, %2;" : "=f"(alo), "=f"(ahi) : "l"(acc2));
        float acc = alo + ahi;
        acc += __shfl_xor_sync(0xffffffffu, acc, 16);   // combine k halves
        if (kh == 0) s_sums[o] = acc;
        __syncthreads();

        int q = m + 1; if (q == 3) q = 0;               // (t+1) % 3

        if (tid < 64) {
            const float hr = s_sums[tid];
            const float hz = s_sums[64 + tid];
            const float hn = s_sums[128 + tid];
            const float rr = fsigmoid(pxr + hr);
            const float zz = fsigmoid(pxz + hz);
            const float nn = ftanh(pxn + rr * hn);
            const float hold = h_buf[m][c * 64 + tid];
            const float hnew = nn + zz * (hold - nn);

            // broadcast h chunk into buf q of all 4 CTAs, then release-arrive
            const uint32_t dst = h_loc + q * (DMODEL * 4);
            const uint32_t bq  = bar_loc + q * 8;
#pragma unroll
            for (int r = 0; r < 4; r++) {
                uint32_t ra;
                asm("mapa.shared::cluster.u32 %0, %1, %2;" : "=r"(ra) : "r"(dst), "r"(r));
                asm volatile("st.shared::cluster.f32 [%0], %1;" :: "r"(ra), "f"(hnew) : "memory");
            }
#pragma unroll
            for (int r = 0; r < 4; r++) {
                uint32_t rb2;
                asm("mapa.shared::cluster.u32 %0, %1, %2;" : "=r"(rb2) : "r"(bq), "r"(r));
                asm volatile("mbarrier.arrive.release.cluster.shared::cluster.b64 _, [%0];"
                             :: "r"(rb2) : "memory");
            }
            // residual write + next-step prefetch
            xb[(long)t * DMODEL + c * 64 + tid] = pxv + hnew;
            if (t + 1 < SEQ) {
                const float* xpt = xpb + (long)(t + 1) * G3;
                pxr = xpt[d]; pxz = xpt[256 + d]; pxn = xpt[512 + d];
                pxv = xb[(long)(t + 1) * DMODEL + c * 64 + tid];
            }
        }
        m = q;
    }
    // quiesce in-flight DSMEM traffic before any CTA exits
    asm volatile("barrier.cluster.arrive.aligned;\n\tbarrier.cluster.wait.aligned;" ::: "memory");
}

// =====================================================================
// Kernel 5a: final LN partials. grid (25 chunks, 32 batch), block 256.
// Each CTA: 40 rows; per-thread partial sum of normalized values.
// =====================================================================
__global__ __launch_bounds__(256) void k_final_part() {
    const int ch = blockIdx.x, b = blockIdx.y;
    const int wid = threadIdx.x >> 5, lane = threadIdx.x & 31;
    const float* xb = g_x + (long)b * SEQ * DMODEL;

    float a0[4] = {0, 0, 0, 0}, a1[4] = {0, 0, 0, 0};
    for (int i = 0; i < 5; i++) {
        const int t = ch * 40 + i * 8 + wid;
        const float4* xr = (const float4*)(xb + (long)t * DMODEL);
        float4 v0 = xr[lane];
        float4 v1 = xr[lane + 32];
        float s1 = v0.x + v0.y + v0.z + v0.w + v1.x + v1.y + v1.z + v1.w;
        float s2 = v0.x * v0.x + v0.y * v0.y + v0.z * v0.z + v0.w * v0.w
                 + v1.x * v1.x + v1.y * v1.y + v1.z * v1.z + v1.w * v1.w;
#pragma unroll
        for (int o = 16; o > 0; o >>= 1) {
            s1 += __shfl_xor_sync(0xffffffffu, s1, o);
            s2 += __shfl_xor_sync(0xffffffffu, s2, o);
        }
        const float mu  = s1 * (1.0f / 256.0f);
        const float var = s2 * (1.0f / 256.0f) - mu * mu;
        const float inv = rsqrtf(var + 1e-5f);
        a0[0] += (v0.x - mu) * inv; a0[1] += (v0.y - mu) * inv;
        a0[2] += (v0.z - mu) * inv; a0[3] += (v0.w - mu) * inv;
        a1[0] += (v1.x - mu) * inv; a1[1] += (v1.y - mu) * inv;
        a1[2] += (v1.z - mu) * inv; a1[3] += (v1.w - mu) * inv;
    }
    // 8 warps hold partials for the same dims -> reduce via SMEM
    __shared__ float red[8][DMODEL];
    float* rw = red[wid];
    *(float4*)&rw[lane * 4]       = *(float4*)a0;
    *(float4*)&rw[128 + lane * 4] = *(float4*)a1;
    __syncthreads();
    const int tid = threadIdx.x;
    if (tid < 64) {
        const int dbase = tid * 4;
        float4 s = make_float4(0, 0, 0, 0);
#pragma unroll
        for (int ww = 0; ww < 8; ww++) {
            float4 v = *(float4*)&red[ww][dbase];
            s.x += v.x; s.y += v.y; s.z += v.z; s.w += v.w;
        }
        *(float4*)&g_part[((long)b * 25 + ch) * DMODEL + dbase] = s;
    }
}

// =====================================================================
// Kernel 5b: deterministic reduce of 25 partials + scale/bias + /SEQ.
// =====================================================================
__global__ __launch_bounds__(256) void k_final_sum(const float* __restrict__ sc,
                                                   const float* __restrict__ bi) {
    const int b = blockIdx.x, tid = threadIdx.x;
    float s = 0.0f;
#pragma unroll 5
    for (int ch = 0; ch < 25; ch++) s += g_part[((long)b * 25 + ch) * DMODEL + tid];
    g_emb[b * DMODEL + tid] = s * (1.0f / (float)SEQ) * sc[tid] + bi[tid];
}

// =====================================================================
// Kernel 6: classification head. grid 32, block 128.
// =====================================================================
__global__ __launch_bounds__(128) void k_head(const float* __restrict__ w1,
                                              const float* __restrict__ b1,
                                              const float* __restrict__ w2,
                                              const float* __restrict__ b2,
                                              float* __restrict__ out) {
    const int b = blockIdx.x, tid = threadIdx.x;
    __shared__ float es[DMODEL];
    __shared__ float h1s[128];
    es[tid]       = g_emb[b * DMODEL + tid];
    es[tid + 128] = g_emb[b * DMODEL + tid + 128];
    __syncthreads();
    float a = b1[tid];
#pragma unroll 8
    for (int dmi = 0; dmi < DMODEL; dmi++) a += es[dmi] * w1[dmi * 128 + tid];
    h1s[tid] = gelu_exact(a);
    __syncthreads();
    if (tid < 8) {
        float o = b2[tid];
#pragma unroll 8
        for (int j = 0; j < 128; j++) o += h1s[j] * w2[j * 8 + tid];
        out[b * 8 + tid] = o;
    }
}

// =====================================================================
// launch
// =====================================================================
extern "C" void kernel_launch(void* const* d_in, const int* in_sizes, int n_in,
                              void* d_out, int out_size) {
    const float* waveform = (const float*)d_in[0];
    const float* conv_w   = (const float*)d_in[1];
    const float* pos_emb  = (const float*)d_in[2];
    const float* ln_scale = (const float*)d_in[3];
    const float* ln_bias  = (const float*)d_in[4];
    const float* w_ih     = (const float*)d_in[5];
    const float* w_hh     = (const float*)d_in[6];
    const float* b_ih     = (const float*)d_in[7];
    const float* b_hh     = (const float*)d_in[8];
    const float* fnorm_s  = (const float*)d_in[9];
    const float* fnorm_b  = (const float*)d_in[10];
    const float* head_w1  = (const float*)d_in[11];
    const float* head_b1  = (const float*)d_in[12];
    const float* head_w2  = (const float*)d_in[13];
    const float* head_b2  = (const float*)d_in[14];
    float* out = (float*)d_out;

    k_conv<<<500, 256>>>(waveform, conv_w, pos_emb);

    for (int lyr = 0; lyr < NLAYERS; lyr++) {
        k_ln<<<4000, 256>>>(ln_scale + lyr * DMODEL, ln_bias + lyr * DMODEL);
        dim3 gg(250, 6);
        k_gemm_xp<<<gg, 256>>>(w_ih + (long)lyr * G3 * DMODEL, b_ih + lyr * G3);
        dim3 gr(4, BATCH);
        k_gru<<<gr, 384>>>(w_hh + (long)lyr * G3 * DMODEL, b_hh + lyr * G3);
    }

    dim3 gf(25, BATCH);
    k_final_part<<<gf, 256>>>();
    k_final_sum<<<BATCH, 256>>>(fnorm_s, fnorm_b);
    k_head<<<BATCH, 128>>>(head_w1, head_b1, head_w2, head_b2, out);
}

// round 7
// speedup vs baseline: 1.3703x; 1.3703x over previous
#include <cuda_runtime.h>
#include <cuda_bf16.h>
#include <math.h>
#include <stdint.h>

// ---------------- problem constants ----------------
#define BATCH   32
#define SEQ     1000
#define DMODEL  256
#define PATCHSZ 160
#define NLAYERS 6
#define G3      768   // 3*DMODEL

// ---------------- scratch (device globals; no allocs allowed) ----------------
__device__ float g_x [BATCH * SEQ * DMODEL];   // residual stream x
__device__ float g_ln[BATCH * SEQ * DMODEL];   // layernorm(x) per layer
__device__ float g_xp[BATCH * SEQ * G3];       // input projection per layer
__device__ float g_emb[BATCH * DMODEL];        // pooled embedding
__device__ float g_part[BATCH * 25 * DMODEL];  // final-LN partial sums

__device__ __forceinline__ float gelu_exact(float v) {
    return 0.5f * v * (1.0f + erff(v * 0.70710678118654752440f));
}
__device__ __forceinline__ float fsigmoid(float v) {
    return __fdividef(1.0f, 1.0f + __expf(-v));
}
__device__ __forceinline__ float ftanh(float v) {
    return 1.0f - __fdividef(2.0f, __expf(2.0f * v) + 1.0f);
}

// packed f32x2 helpers
__device__ __forceinline__ unsigned long long pk2(float lo, float hi) {
    unsigned long long r;
    asm("mov.b64 %0, {%1, %2};" : "=l"(r) : "f"(lo), "f"(hi));
    return r;
}
__device__ __forceinline__ void upk2(unsigned long long v, float& lo, float& hi) {
    asm("mov.b64 {%0, %1}, %2;" : "=f"(lo), "=f"(hi) : "l"(v));
}
__device__ __forceinline__ unsigned long long fma2(unsigned long long a,
                                                   unsigned long long b,
                                                   unsigned long long c) {
    unsigned long long r;
    asm("fma.rn.f32x2 %0, %1, %2, %3;" : "=l"(r) : "l"(a), "l"(b), "l"(c));
    return r;
}

// =====================================================================
// Kernel 1: patchify conv (k=stride=160) + exact GELU + pos emb -> g_x
// =====================================================================
__global__ __launch_bounds__(256) void k_conv(const float* __restrict__ wave,
                                              const float* __restrict__ cw,
                                              const float* __restrict__ pos) {
    __shared__ __align__(16) float sw[64 * PATCHSZ];   // 40 KB
    const int tid = threadIdx.x;
    const long base = (long)blockIdx.x * 64 * PATCHSZ;

    const float4* src = (const float4*)(wave + base);
    float4* dst = (float4*)sw;
#pragma unroll
    for (int i = 0; i < 10; i++) dst[tid + i * 256] = src[tid + i * 256];

    float creg[PATCHSZ];
#pragma unroll
    for (int p = 0; p < PATCHSZ; p++) creg[p] = cw[p * DMODEL + tid];
    __syncthreads();

    const int row0 = blockIdx.x * 64;
    for (int r = 0; r < 64; r++) {
        const float4* wv = (const float4*)(sw + r * PATCHSZ);
        float acc = 0.0f;
#pragma unroll
        for (int i = 0; i < PATCHSZ / 4; i++) {
            float4 v = wv[i];
            acc += v.x * creg[4 * i + 0];
            acc += v.y * creg[4 * i + 1];
            acc += v.z * creg[4 * i + 2];
            acc += v.w * creg[4 * i + 3];
        }
        const int row = row0 + r;
        const int s = row % SEQ;
        g_x[(long)row * DMODEL + tid] = gelu_exact(acc) + pos[s * DMODEL + tid];
    }
}

// =====================================================================
// Kernel 2: layernorm over last dim (256). one warp per row.
// =====================================================================
__global__ __launch_bounds__(256) void k_ln(const float* __restrict__ sc,
                                            const float* __restrict__ bi) {
    const int wid = threadIdx.x >> 5, lane = threadIdx.x & 31;
    const long row = (long)blockIdx.x * 8 + wid;
    const float4* xr = (const float4*)(g_x + row * DMODEL);
    float4 v0 = xr[lane];
    float4 v1 = xr[lane + 32];
    float s1 = v0.x + v0.y + v0.z + v0.w + v1.x + v1.y + v1.z + v1.w;
    float s2 = v0.x * v0.x + v0.y * v0.y + v0.z * v0.z + v0.w * v0.w
             + v1.x * v1.x + v1.y * v1.y + v1.z * v1.z + v1.w * v1.w;
#pragma unroll
    for (int o = 16; o > 0; o >>= 1) {
        s1 += __shfl_xor_sync(0xffffffffu, s1, o);
        s2 += __shfl_xor_sync(0xffffffffu, s2, o);
    }
    const float mu  = s1 * (1.0f / 256.0f);
    const float var = s2 * (1.0f / 256.0f) - mu * mu;
    const float inv = rsqrtf(var + 1e-5f);

    const int d0 = lane * 4, d1 = 128 + lane * 4;
    float4 sa = *(const float4*)(sc + d0), sb = *(const float4*)(sc + d1);
    float4 ba = *(const float4*)(bi + d0), bb = *(const float4*)(bi + d1);
    float4 o0, o1;
    o0.x = (v0.x - mu) * inv * sa.x + ba.x;  o0.y = (v0.y - mu) * inv * sa.y + ba.y;
    o0.z = (v0.z - mu) * inv * sa.z + ba.z;  o0.w = (v0.w - mu) * inv * sa.w + ba.w;
    o1.x = (v1.x - mu) * inv * sb.x + bb.x;  o1.y = (v1.y - mu) * inv * sb.y + bb.y;
    o1.z = (v1.z - mu) * inv * sb.z + bb.z;  o1.w = (v1.w - mu) * inv * sb.w + bb.w;
    float4* outr = (float4*)(g_ln + row * DMODEL);
    outr[lane] = o0;
    outr[lane + 32] = o1;
}

// =====================================================================
// Kernel 3: xp = g_ln[32000,256] @ W_ih^T[256,768] + b_ih -> g_xp
// 128x128 tile, K-chunk 32, 8x8 microtile, FFMA2 (f32x2) inner loop:
// accumulators paired along j; b loaded as u64 pairs, a splatted.
// =====================================================================
__global__ __launch_bounds__(256) void k_gemm_xp(const float* __restrict__ W,
                                                 const float* __restrict__ bias) {
    __shared__ __align__(16) float As[128][36];   // [row][k] padded
    __shared__ __align__(16) float Bs[32][132];   // [k][col] padded (transposed)
    const int tid = threadIdx.x;
    const int tx = tid & 15, ty = tid >> 4;
    const int row0 = blockIdx.x * 128, col0 = blockIdx.y * 128;

    unsigned long long acc2[8][4];
#pragma unroll
    for (int i = 0; i < 8; i++)
#pragma unroll
        for (int j = 0; j < 4; j++) acc2[i][j] = 0ull;

    for (int k0 = 0; k0 < DMODEL; k0 += 32) {
#pragma unroll
        for (int it = 0; it < 4; it++) {
            int m = tid + it * 256;
            int r = m >> 3, kq = (m & 7) * 4;
            float4 v = *(const float4*)(g_ln + (long)(row0 + r) * DMODEL + k0 + kq);
            *(float4*)&As[r][kq] = v;
        }
#pragma unroll
        for (int it = 0; it < 4; it++) {
            int m = tid + it * 256;
            int cc = m >> 3, kq = (m & 7) * 4;
            float4 v = *(const float4*)(W + (long)(col0 + cc) * DMODEL + k0 + kq);
            Bs[kq + 0][cc] = v.x; Bs[kq + 1][cc] = v.y;
            Bs[kq + 2][cc] = v.z; Bs[kq + 3][cc] = v.w;
        }
        __syncthreads();
#pragma unroll
        for (int kk = 0; kk < 32; kk++) {
            // b: 8 consecutive floats -> 4 packed f32x2 (16B-aligned LDS)
            ulonglong2 q0 = *(const ulonglong2*)&Bs[kk][tx * 8];
            ulonglong2 q1 = *(const ulonglong2*)&Bs[kk][tx * 8 + 4];
            unsigned long long bp0 = q0.x, bp1 = q0.y, bp2 = q1.x, bp3 = q1.y;
#pragma unroll
            for (int i = 0; i < 8; i++) {
                const float a = As[ty * 8 + i][kk];
                const unsigned long long as2 = pk2(a, a);
                acc2[i][0] = fma2(as2, bp0, acc2[i][0]);
                acc2[i][1] = fma2(as2, bp1, acc2[i][1]);
                acc2[i][2] = fma2(as2, bp2, acc2[i][2]);
                acc2[i][3] = fma2(as2, bp3, acc2[i][3]);
            }
        }
        __syncthreads();
    }
#pragma unroll
    for (int i = 0; i < 8; i++) {
        const long row = row0 + ty * 8 + i;
        const int col = col0 + tx * 8;
        float o[8];
#pragma unroll
        for (int j = 0; j < 4; j++) upk2(acc2[i][j], o[2 * j], o[2 * j + 1]);
        float4 v0, v1;
        v0.x = o[0] + bias[col + 0]; v0.y = o[1] + bias[col + 1];
        v0.z = o[2] + bias[col + 2]; v0.w = o[3] + bias[col + 3];
        v1.x = o[4] + bias[col + 4]; v1.y = o[5] + bias[col + 5];
        v1.z = o[6] + bias[col + 6]; v1.w = o[7] + bias[col + 7];
        *(float4*)(g_xp + row * G3 + col)     = v0;
        *(float4*)(g_xp + row * G3 + col + 4) = v1;
    }
}

// =====================================================================
// Kernel 4: GRU recurrence. cluster(4) per batch element, grid (4,32),
// block 384. Weights register-resident as f32x2 pairs (FFMA2 matvec).
// h double-buffered in SMEM; chunk broadcast via st.shared::cluster;
// ONE barrier.cluster per step (R3-proven sync: reads of buf p at step t
// precede the step-t barrier; writes to buf p at step t+1 follow it).
// =====================================================================
__global__ void __cluster_dims__(4, 1, 1) __launch_bounds__(384, 1)
k_gru(const float* __restrict__ whh, const float* __restrict__ bhh) {
    __shared__ __align__(16) float h_buf[2][DMODEL];
    __shared__ float s_sums[192];

    const int c   = blockIdx.x;          // cluster rank 0..3
    const int b   = blockIdx.y;
    const int tid = threadIdx.x;
    const int w   = tid >> 5, l = tid & 31;
    const int o   = w * 16 + (l & 15);   // 0..191: CTA-local output index
    const int kh  = l >> 4;              // k half: 0 -> k[0,128), 1 -> k[128,256)
    const int gg  = o >> 6, dd = o & 63;
    const int R   = gg * DMODEL + c * 64 + dd;   // gate row in [0,768)

    // weight slice: 128 floats = 64 f32x2 pairs in registers
    unsigned long long wreg[64];
    {
        const ulonglong2* wp = (const ulonglong2*)(whh + (long)R * DMODEL + kh * 128);
#pragma unroll
        for (int i = 0; i < 32; i++) { ulonglong2 t2 = wp[i]; wreg[2*i] = t2.x; wreg[2*i+1] = t2.y; }
    }
    const float breg = (kh == 0) ? bhh[R] : 0.0f;

    // init both h buffers to 0
    for (int i = tid; i < 2 * DMODEL; i += 384) ((float*)h_buf)[i] = 0.0f;

    const float* xpb = g_xp + (long)b * SEQ * G3;
    float* xb = g_x + (long)b * SEQ * DMODEL;
    const int d = c * 64 + tid;          // gate threads: tid < 64

    float pxr = 0.f, pxz = 0.f, pxn = 0.f, pxv = 0.f;
    float hold = 0.0f;                   // this thread's own h value (reg-resident)
    if (tid < 64) {
        pxr = xpb[d]; pxz = xpb[256 + d]; pxn = xpb[512 + d];
        pxv = xb[c * 64 + tid];
    }
    asm volatile("barrier.cluster.arrive.aligned;\n\tbarrier.cluster.wait.aligned;" ::: "memory");

    for (int t = 0; t < SEQ; t++) {
        const int p = t & 1;
        // ---- matvec: 64 packed FFMA2 against h_buf[p] ----
        unsigned long long acc2 = pk2(breg, 0.0f);
        const ulonglong2* hv = (const ulonglong2*)&h_buf[p][kh * 128];
#pragma unroll
        for (int i = 0; i < 32; i++) {
            ulonglong2 h2 = hv[i];
            acc2 = fma2(wreg[2 * i],     h2.x, acc2);
            acc2 = fma2(wreg[2 * i + 1], h2.y, acc2);
        }
        float alo, ahi;
        upk2(acc2, alo, ahi);
        float acc = alo + ahi;
        acc += __shfl_xor_sync(0xffffffffu, acc, 16);   // combine k halves
        if (kh == 0) s_sums[o] = acc;
        __syncthreads();

        if (tid < 64) {
            const float hr = s_sums[tid];
            const float hz = s_sums[64 + tid];
            const float hn = s_sums[128 + tid];
            const float rr = fsigmoid(pxr + hr);
            const float zz = fsigmoid(pxz + hz);
            const float nn = ftanh(pxn + rr * hn);
            const float hnew = nn + zz * (hold - nn);
            hold = hnew;

            // broadcast h chunk to all 4 CTAs' next buffer
            uint32_t la = (uint32_t)__cvta_generic_to_shared(&h_buf[p ^ 1][c * 64 + tid]);
#pragma unroll
            for (int r = 0; r < 4; r++) {
                uint32_t ra;
                asm("mapa.shared::cluster.u32 %0, %1, %2;" : "=r"(ra) : "r"(la), "r"(r));
                asm volatile("st.shared::cluster.f32 [%0], %1;" :: "r"(ra), "f"(hnew) : "memory");
            }
            // residual: x_{l+1} = x_l + h_t  (pxv prefetched -> pure store)
            xb[(long)t * DMODEL + c * 64 + tid] = pxv + hnew;

            // prefetch next step (consumed next gate phase; latency hidden)
            if (t + 1 < SEQ) {
                const float* xpt = xpb + (long)(t + 1) * G3;
                pxr = xpt[d]; pxz = xpt[256 + d]; pxn = xpt[512 + d];
                pxv = xb[(long)(t + 1) * DMODEL + c * 64 + tid];
            }
        }
        // cluster barrier: release remote h stores / acquire peers'
        asm volatile("barrier.cluster.arrive.aligned;\n\tbarrier.cluster.wait.aligned;" ::: "memory");
    }
}

// =====================================================================
// Kernel 5a: final LN partials. grid (25 chunks, 32 batch), block 256.
// =====================================================================
__global__ __launch_bounds__(256) void k_final_part() {
    const int ch = blockIdx.x, b = blockIdx.y;
    const int wid = threadIdx.x >> 5, lane = threadIdx.x & 31;
    const float* xb = g_x + (long)b * SEQ * DMODEL;

    float a0[4] = {0, 0, 0, 0}, a1[4] = {0, 0, 0, 0};
    for (int i = 0; i < 5; i++) {
        const int t = ch * 40 + i * 8 + wid;
        const float4* xr = (const float4*)(xb + (long)t * DMODEL);
        float4 v0 = xr[lane];
        float4 v1 = xr[lane + 32];
        float s1 = v0.x + v0.y + v0.z + v0.w + v1.x + v1.y + v1.z + v1.w;
        float s2 = v0.x * v0.x + v0.y * v0.y + v0.z * v0.z + v0.w * v0.w
                 + v1.x * v1.x + v1.y * v1.y + v1.z * v1.z + v1.w * v1.w;
#pragma unroll
        for (int o = 16; o > 0; o >>= 1) {
            s1 += __shfl_xor_sync(0xffffffffu, s1, o);
            s2 += __shfl_xor_sync(0xffffffffu, s2, o);
        }
        const float mu  = s1 * (1.0f / 256.0f);
        const float var = s2 * (1.0f / 256.0f) - mu * mu;
        const float inv = rsqrtf(var + 1e-5f);
        a0[0] += (v0.x - mu) * inv; a0[1] += (v0.y - mu) * inv;
        a0[2] += (v0.z - mu) * inv; a0[3] += (v0.w - mu) * inv;
        a1[0] += (v1.x - mu) * inv; a1[1] += (v1.y - mu) * inv;
        a1[2] += (v1.z - mu) * inv; a1[3] += (v1.w - mu) * inv;
    }
    __shared__ float red[8][DMODEL];
    float* rw = red[wid];
    *(float4*)&rw[lane * 4]       = *(float4*)a0;
    *(float4*)&rw[128 + lane * 4] = *(float4*)a1;
    __syncthreads();
    const int tid = threadIdx.x;
    if (tid < 64) {
        const int dbase = tid * 4;
        float4 s = make_float4(0, 0, 0, 0);
#pragma unroll
        for (int ww = 0; ww < 8; ww++) {
            float4 v = *(float4*)&red[ww][dbase];
            s.x += v.x; s.y += v.y; s.z += v.z; s.w += v.w;
        }
        *(float4*)&g_part[((long)b * 25 + ch) * DMODEL + dbase] = s;
    }
}

// =====================================================================
// Kernel 5b: deterministic reduce of 25 partials + scale/bias + /SEQ.
// =====================================================================
__global__ __launch_bounds__(256) void k_final_sum(const float* __restrict__ sc,
                                                   const float* __restrict__ bi) {
    const int b = blockIdx.x, tid = threadIdx.x;
    float s = 0.0f;
#pragma unroll 5
    for (int ch = 0; ch < 25; ch++) s += g_part[((long)b * 25 + ch) * DMODEL + tid];
    g_emb[b * DMODEL + tid] = s * (1.0f / (float)SEQ) * sc[tid] + bi[tid];
}

// =====================================================================
// Kernel 6: classification head. grid 32, block 128.
// =====================================================================
__global__ __launch_bounds__(128) void k_head(const float* __restrict__ w1,
                                              const float* __restrict__ b1,
                                              const float* __restrict__ w2,
                                              const float* __restrict__ b2,
                                              float* __restrict__ out) {
    const int b = blockIdx.x, tid = threadIdx.x;
    __shared__ float es[DMODEL];
    __shared__ float h1s[128];
    es[tid]       = g_emb[b * DMODEL + tid];
    es[tid + 128] = g_emb[b * DMODEL + tid + 128];
    __syncthreads();
    float a = b1[tid];
#pragma unroll 8
    for (int dmi = 0; dmi < DMODEL; dmi++) a += es[dmi] * w1[dmi * 128 + tid];
    h1s[tid] = gelu_exact(a);
    __syncthreads();
    if (tid < 8) {
        float o = b2[tid];
#pragma unroll 8
        for (int j = 0; j < 128; j++) o += h1s[j] * w2[j * 8 + tid];
        out[b * 8 + tid] = o;
    }
}

// =====================================================================
// launch
// =====================================================================
extern "C" void kernel_launch(void* const* d_in, const int* in_sizes, int n_in,
                              void* d_out, int out_size) {
    const float* waveform = (const float*)d_in[0];
    const float* conv_w   = (const float*)d_in[1];
    const float* pos_emb  = (const float*)d_in[2];
    const float* ln_scale = (const float*)d_in[3];
    const float* ln_bias  = (const float*)d_in[4];
    const float* w_ih     = (const float*)d_in[5];
    const float* w_hh     = (const float*)d_in[6];
    const float* b_ih     = (const float*)d_in[7];
    const float* b_hh     = (const float*)d_in[8];
    const float* fnorm_s  = (const float*)d_in[9];
    const float* fnorm_b  = (const float*)d_in[10];
    const float* head_w1  = (const float*)d_in[11];
    const float* head_b1  = (const float*)d_in[12];
    const float* head_w2  = (const float*)d_in[13];
    const float* head_b2  = (const float*)d_in[14];
    float* out = (float*)d_out;

    k_conv<<<500, 256>>>(waveform, conv_w, pos_emb);

    for (int lyr = 0; lyr < NLAYERS; lyr++) {
        k_ln<<<4000, 256>>>(ln_scale + lyr * DMODEL, ln_bias + lyr * DMODEL);
        dim3 gg(250, 6);
        k_gemm_xp<<<gg, 256>>>(w_ih + (long)lyr * G3 * DMODEL, b_ih + lyr * G3);
        dim3 gr(4, BATCH);
        k_gru<<<gr, 384>>>(w_hh + (long)lyr * G3 * DMODEL, b_hh + lyr * G3);
    }

    dim3 gf(25, BATCH);
    k_final_part<<<gf, 256>>>();
    k_final_sum<<<BATCH, 256>>>(fnorm_s, fnorm_b);
    k_head<<<BATCH, 128>>>(head_w1, head_b1, head_w2, head_b2, out);
}

// round 11
// speedup vs baseline: 1.9650x; 1.4340x over previous
#include <cuda_runtime.h>
#include <cuda_bf16.h>
#include <math.h>
#include <stdint.h>

// ---------------- problem constants ----------------
#define BATCH   32
#define SEQ     1000
#define DMODEL  256
#define PATCHSZ 160
#define NLAYERS 6
#define G3      768   // 3*DMODEL

// ---------------- scratch (device globals; no allocs allowed) ----------------
__device__ float g_x [BATCH * SEQ * DMODEL];   // residual stream x
__device__ float g_ln[BATCH * SEQ * DMODEL];   // layernorm(x) per layer
__device__ float g_xp[BATCH * SEQ * G3];       // input projection per layer
__device__ float g_emb[BATCH * DMODEL];        // pooled embedding
__device__ float g_part[BATCH * 25 * DMODEL];  // final-LN partial sums

__device__ __forceinline__ float gelu_exact(float v) {
    return 0.5f * v * (1.0f + erff(v * 0.70710678118654752440f));
}
__device__ __forceinline__ float fsigmoid(float v) {
    return __fdividef(1.0f, 1.0f + __expf(-v));
}
__device__ __forceinline__ float ftanh(float v) {
    return 1.0f - __fdividef(2.0f, __expf(2.0f * v) + 1.0f);
}

// packed f32x2 helpers
__device__ __forceinline__ unsigned long long pk2(float lo, float hi) {
    unsigned long long r;
    asm("mov.b64 %0, {%1, %2};" : "=l"(r) : "f"(lo), "f"(hi));
    return r;
}
__device__ __forceinline__ void upk2(unsigned long long v, float& lo, float& hi) {
    asm("mov.b64 {%0, %1}, %2;" : "=f"(lo), "=f"(hi) : "l"(v));
}
__device__ __forceinline__ unsigned long long fma2(unsigned long long a,
                                                   unsigned long long b,
                                                   unsigned long long c) {
    unsigned long long r;
    asm("fma.rn.f32x2 %0, %1, %2, %3;" : "=l"(r) : "l"(a), "l"(b), "l"(c));
    return r;
}

// local mbarrier parity wait (acquire.cta — data arrives via async proxy tx)
__device__ __forceinline__ void mbar_wait(uint32_t mb, unsigned par) {
    unsigned done;
    asm volatile(
        "{\n\t.reg .pred p;\n\t"
        "mbarrier.try_wait.parity.acquire.cta.shared::cta.b64 p, [%1], %2;\n\t"
        "selp.b32 %0, 1, 0, p;\n\t}"
        : "=r"(done) : "r"(mb), "r"(par) : "memory");
    if (!done) {
        asm volatile(
            "{\n\t.reg .pred P1;\n\t"
            "WL%=:\n\t"
            "mbarrier.try_wait.parity.acquire.cta.shared::cta.b64 P1, [%0], %1, 0x989680;\n\t"
            "@P1 bra.uni WD%=;\n\t"
            "bra.uni WL%=;\n\t"
            "WD%=:\n\t}"
            :: "r"(mb), "r"(par) : "memory");
    }
}

// =====================================================================
// Kernel 1: patchify conv (k=stride=160) + exact GELU + pos emb -> g_x
// =====================================================================
__global__ __launch_bounds__(256) void k_conv(const float* __restrict__ wave,
                                              const float* __restrict__ cw,
                                              const float* __restrict__ pos) {
    __shared__ __align__(16) float sw[64 * PATCHSZ];   // 40 KB
    const int tid = threadIdx.x;
    const long base = (long)blockIdx.x * 64 * PATCHSZ;

    const float4* src = (const float4*)(wave + base);
    float4* dst = (float4*)sw;
#pragma unroll
    for (int i = 0; i < 10; i++) dst[tid + i * 256] = src[tid + i * 256];

    float creg[PATCHSZ];
#pragma unroll
    for (int p = 0; p < PATCHSZ; p++) creg[p] = cw[p * DMODEL + tid];
    __syncthreads();

    const int row0 = blockIdx.x * 64;
    for (int r = 0; r < 64; r++) {
        const float4* wv = (const float4*)(sw + r * PATCHSZ);
        float acc = 0.0f;
#pragma unroll
        for (int i = 0; i < PATCHSZ / 4; i++) {
            float4 v = wv[i];
            acc += v.x * creg[4 * i + 0];
            acc += v.y * creg[4 * i + 1];
            acc += v.z * creg[4 * i + 2];
            acc += v.w * creg[4 * i + 3];
        }
        const int row = row0 + r;
        const int s = row % SEQ;
        g_x[(long)row * DMODEL + tid] = gelu_exact(acc) + pos[s * DMODEL + tid];
    }
}

// =====================================================================
// Kernel 2: layernorm over last dim (256). one warp per row.
// =====================================================================
__global__ __launch_bounds__(256) void k_ln(const float* __restrict__ sc,
                                            const float* __restrict__ bi) {
    const int wid = threadIdx.x >> 5, lane = threadIdx.x & 31;
    const long row = (long)blockIdx.x * 8 + wid;
    const float4* xr = (const float4*)(g_x + row * DMODEL);
    float4 v0 = xr[lane];
    float4 v1 = xr[lane + 32];
    float s1 = v0.x + v0.y + v0.z + v0.w + v1.x + v1.y + v1.z + v1.w;
    float s2 = v0.x * v0.x + v0.y * v0.y + v0.z * v0.z + v0.w * v0.w
             + v1.x * v1.x + v1.y * v1.y + v1.z * v1.z + v1.w * v1.w;
#pragma unroll
    for (int o = 16; o > 0; o >>= 1) {
        s1 += __shfl_xor_sync(0xffffffffu, s1, o);
        s2 += __shfl_xor_sync(0xffffffffu, s2, o);
    }
    const float mu  = s1 * (1.0f / 256.0f);
    const float var = s2 * (1.0f / 256.0f) - mu * mu;
    const float inv = rsqrtf(var + 1e-5f);

    const int d0 = lane * 4, d1 = 128 + lane * 4;
    float4 sa = *(const float4*)(sc + d0), sb = *(const float4*)(sc + d1);
    float4 ba = *(const float4*)(bi + d0), bb = *(const float4*)(bi + d1);
    float4 o0, o1;
    o0.x = (v0.x - mu) * inv * sa.x + ba.x;  o0.y = (v0.y - mu) * inv * sa.y + ba.y;
    o0.z = (v0.z - mu) * inv * sa.z + ba.z;  o0.w = (v0.w - mu) * inv * sa.w + ba.w;
    o1.x = (v1.x - mu) * inv * sb.x + bb.x;  o1.y = (v1.y - mu) * inv * sb.y + bb.y;
    o1.z = (v1.z - mu) * inv * sb.z + bb.z;  o1.w = (v1.w - mu) * inv * sb.w + bb.w;
    float4* outr = (float4*)(g_ln + row * DMODEL);
    outr[lane] = o0;
    outr[lane + 32] = o1;
}

// =====================================================================
// Kernel 3: xp = g_ln[32000,256] @ W_ih^T[256,768] + b_ih -> g_xp
// 128x128 tile, K-chunk 32, 8x8 microtile, FFMA2 (f32x2) inner loop.
// =====================================================================
__global__ __launch_bounds__(256) void k_gemm_xp(const float* __restrict__ W,
                                                 const float* __restrict__ bias) {
    __shared__ __align__(16) float As[128][36];   // [row][k] padded
    __shared__ __align__(16) float Bs[32][132];   // [k][col] padded (transposed)
    const int tid = threadIdx.x;
    const int tx = tid & 15, ty = tid >> 4;
    const int row0 = blockIdx.x * 128, col0 = blockIdx.y * 128;

    unsigned long long acc2[8][4];
#pragma unroll
    for (int i = 0; i < 8; i++)
#pragma unroll
        for (int j = 0; j < 4; j++) acc2[i][j] = 0ull;

    for (int k0 = 0; k0 < DMODEL; k0 += 32) {
#pragma unroll
        for (int it = 0; it < 4; it++) {
            int m = tid + it * 256;
            int r = m >> 3, kq = (m & 7) * 4;
            float4 v = *(const float4*)(g_ln + (long)(row0 + r) * DMODEL + k0 + kq);
            *(float4*)&As[r][kq] = v;
        }
#pragma unroll
        for (int it = 0; it < 4; it++) {
            int m = tid + it * 256;
            int cc = m >> 3, kq = (m & 7) * 4;
            float4 v = *(const float4*)(W + (long)(col0 + cc) * DMODEL + k0 + kq);
            Bs[kq + 0][cc] = v.x; Bs[kq + 1][cc] = v.y;
            Bs[kq + 2][cc] = v.z; Bs[kq + 3][cc] = v.w;
        }
        __syncthreads();
#pragma unroll
        for (int kk = 0; kk < 32; kk++) {
            ulonglong2 q0 = *(const ulonglong2*)&Bs[kk][tx * 8];
            ulonglong2 q1 = *(const ulonglong2*)&Bs[kk][tx * 8 + 4];
            unsigned long long bp0 = q0.x, bp1 = q0.y, bp2 = q1.x, bp3 = q1.y;
#pragma unroll
            for (int i = 0; i < 8; i++) {
                const float a = As[ty * 8 + i][kk];
                const unsigned long long as2 = pk2(a, a);
                acc2[i][0] = fma2(as2, bp0, acc2[i][0]);
                acc2[i][1] = fma2(as2, bp1, acc2[i][1]);
                acc2[i][2] = fma2(as2, bp2, acc2[i][2]);
                acc2[i][3] = fma2(as2, bp3, acc2[i][3]);
            }
        }
        __syncthreads();
    }
#pragma unroll
    for (int i = 0; i < 8; i++) {
        const long row = row0 + ty * 8 + i;
        const int col = col0 + tx * 8;
        float o[8];
#pragma unroll
        for (int j = 0; j < 4; j++) upk2(acc2[i][j], o[2 * j], o[2 * j + 1]);
        float4 v0, v1;
        v0.x = o[0] + bias[col + 0]; v0.y = o[1] + bias[col + 1];
        v0.z = o[2] + bias[col + 2]; v0.w = o[3] + bias[col + 3];
        v1.x = o[4] + bias[col + 4]; v1.y = o[5] + bias[col + 5];
        v1.z = o[6] + bias[col + 6]; v1.w = o[7] + bias[col + 7];
        *(float4*)(g_xp + row * G3 + col)     = v0;
        *(float4*)(g_xp + row * G3 + col + 4) = v1;
    }
}

// =====================================================================
// Kernel 4: GRU recurrence. cluster(4) per batch, grid (4,32), block 384.
// FFMA2 matvec, register-resident weights. h TRIPLE-buffered; per-step
// sync via st.async.shared::cluster.mbarrier::complete_tx (data stores
// carry the signal; NO cluster barrier / NO L1 flush in the loop).
// Safety: a CTA at step t implies bar[t%3] full, which needs every CTA's
// step t-1 stores, which follow their step t-2 reads -> writing buffer
// (t+1)%3 == (t-2)%3 is WAR-safe. Intra-CTA skew bounded by the per-step
// __syncthreads, so a barrier phase cannot complete twice before all
// waiters of the prior phase observe it.
// =====================================================================
__global__ void __cluster_dims__(4, 1, 1) __launch_bounds__(384, 1)
k_gru(const float* __restrict__ whh, const float* __restrict__ bhh) {
    __shared__ __align__(16) float h_buf[3][DMODEL];
    __shared__ float s_sums[192];
    __shared__ __align__(8) unsigned long long s_bar[3];

    const int c   = blockIdx.x;          // cluster rank 0..3
    const int b   = blockIdx.y;
    const int tid = threadIdx.x;
    const int w   = tid >> 5, l = tid & 31;
    const int o   = w * 16 + (l & 15);   // 0..191: CTA-local output index
    const int kh  = l >> 4;              // k half: 0 -> k[0,128), 1 -> k[128,256)
    const int gg  = o >> 6, dd = o & 63;
    const int R   = gg * DMODEL + c * 64 + dd;   // gate row in [0,768)

    // weight slice: 128 floats = 64 f32x2 pairs in registers
    unsigned long long wreg[64];
    {
        const ulonglong2* wp = (const ulonglong2*)(whh + (long)R * DMODEL + kh * 128);
#pragma unroll
        for (int i = 0; i < 32; i++) { ulonglong2 t2 = wp[i]; wreg[2*i] = t2.x; wreg[2*i+1] = t2.y; }
    }
    const float breg = (kh == 0) ? bhh[R] : 0.0f;

    // init h buffers + mbarriers (count=1: the local expect_tx arrive)
    for (int i = tid; i < 3 * DMODEL; i += 384) ((float*)h_buf)[i] = 0.0f;
    if (tid == 0) {
#pragma unroll
        for (int mm = 0; mm < 3; mm++) {
            uint32_t ba = (uint32_t)__cvta_generic_to_shared(&s_bar[mm]);
            asm volatile("mbarrier.init.shared.b64 [%0], %1;" :: "r"(ba), "r"(1u) : "memory");
        }
    }
    __syncthreads();
    // bars + zeroed buffers visible cluster-wide before any st.async
    asm volatile("barrier.cluster.arrive.aligned;\n\tbarrier.cluster.wait.aligned;" ::: "memory");

    const uint32_t bar_loc = (uint32_t)__cvta_generic_to_shared(&s_bar[0]);
    const uint32_t h_loc   = (uint32_t)__cvta_generic_to_shared(&h_buf[0][c * 64 + (tid & 63)]);

    const float* xpb = g_xp + (long)b * SEQ * G3;
    float* xb = g_x + (long)b * SEQ * DMODEL;
    const int d = c * 64 + tid;          // gate threads: tid < 64

    float pxr = 0.f, pxz = 0.f, pxn = 0.f, pxv = 0.f;
    float hold = 0.0f;
    if (tid < 64) {
        pxr = xpb[d]; pxz = xpb[256 + d]; pxn = xpb[512 + d];
        pxv = xb[c * 64 + tid];
    }

    unsigned ph[3] = {0u, 0u, 0u};       // const-indexed after unroll -> regs

    // steps 0..998 unrolled by 3 (m compile-time); tail step 999 after.
    for (int tb = 0; tb < SEQ - 1; tb += 3) {
#pragma unroll
        for (int sub = 0; sub < 3; sub++) {
            const int t = tb + sub;
            const int m = sub;
            const int q = (sub + 1) % 3;

            // post expect_tx for next buffer early (1024 B = 4 CTA x 64 x 4B)
            if (tid == 0) {
                asm volatile("mbarrier.arrive.expect_tx.shared.b64 _, [%0], %1;"
                             :: "r"(bar_loc + q * 8), "r"(1024u) : "memory");
            }
            if (t) { mbar_wait(bar_loc + m * 8, ph[m]); ph[m] ^= 1u; }

            // ---- matvec: 64 packed FFMA2 against h_buf[m] ----
            unsigned long long acc2 = pk2(breg, 0.0f);
            const ulonglong2* hv = (const ulonglong2*)&h_buf[m][kh * 128];
#pragma unroll
            for (int i = 0; i < 32; i++) {
                ulonglong2 h2 = hv[i];
                acc2 = fma2(wreg[2 * i],     h2.x, acc2);
                acc2 = fma2(wreg[2 * i + 1], h2.y, acc2);
            }
            float alo, ahi;
            upk2(acc2, alo, ahi);
            float acc = alo + ahi;
            acc += __shfl_xor_sync(0xffffffffu, acc, 16);
            if (kh == 0) s_sums[o] = acc;
            __syncthreads();

            if (tid < 64) {
                const float hr = s_sums[tid];
                const float hz = s_sums[64 + tid];
                const float hn = s_sums[128 + tid];
                const float rr = fsigmoid(pxr + hr);
                const float zz = fsigmoid(pxz + hz);
                const float nn = ftanh(pxn + rr * hn);
                const float hnew = nn + zz * (hold - nn);
                hold = hnew;

                // broadcast h to buf q of all 4 CTAs; stores carry the signal
                const uint32_t dst = h_loc + q * (DMODEL * 4);
                const uint32_t bq  = bar_loc + q * 8;
#pragma unroll
                for (int r = 0; r < 4; r++) {
                    uint32_t ra, rb;
                    asm("mapa.shared::cluster.u32 %0, %1, %2;" : "=r"(ra) : "r"(dst), "r"(r));
                    asm("mapa.shared::cluster.u32 %0, %1, %2;" : "=r"(rb) : "r"(bq),  "r"(r));
                    asm volatile(
                        "st.async.shared::cluster.mbarrier::complete_tx::bytes.f32 [%0], %1, [%2];"
                        :: "r"(ra), "f"(hnew), "r"(rb) : "memory");
                }
                // residual write + next-step prefetch (latency hidden)
                xb[(long)t * DMODEL + c * 64 + tid] = pxv + hnew;
                const float* xpt = xpb + (long)(t + 1) * G3;
                pxr = xpt[d]; pxz = xpt[256 + d]; pxn = xpt[512 + d];
                pxv = xb[(long)(t + 1) * DMODEL + c * 64 + tid];
            }
        }
    }
    // ---- tail step t = SEQ-1 (m = 0): no broadcast, residual only ----
    {
        const int t = SEQ - 1;
        mbar_wait(bar_loc + 0, ph[0]);
        unsigned long long acc2 = pk2(breg, 0.0f);
        const ulonglong2* hv = (const ulonglong2*)&h_buf[0][kh * 128];
#pragma unroll
        for (int i = 0; i < 32; i++) {
            ulonglong2 h2 = hv[i];
            acc2 = fma2(wreg[2 * i],     h2.x, acc2);
            acc2 = fma2(wreg[2 * i + 1], h2.y, acc2);
        }
        float alo, ahi;
        upk2(acc2, alo, ahi);
        float acc = alo + ahi;
        acc += __shfl_xor_sync(0xffffffffu, acc, 16);
        if (kh == 0) s_sums[o] = acc;
        __syncthreads();
        if (tid < 64) {
            const float hr = s_sums[tid];
            const float hz = s_sums[64 + tid];
            const float hn = s_sums[128 + tid];
            const float rr = fsigmoid(pxr + hr);
            const float zz = fsigmoid(pxz + hz);
            const float nn = ftanh(pxn + rr * hn);
            const float hnew = nn + zz * (hold - nn);
            xb[(long)t * DMODEL + c * 64 + tid] = pxv + hnew;
        }
    }
    // symmetric exit (no DSMEM traffic can target an exited CTA)
    asm volatile("barrier.cluster.arrive.aligned;\n\tbarrier.cluster.wait.aligned;" ::: "memory");
}

// =====================================================================
// Kernel 5a: final LN partials. grid (25 chunks, 32 batch), block 256.
// =====================================================================
__global__ __launch_bounds__(256) void k_final_part() {
    const int ch = blockIdx.x, b = blockIdx.y;
    const int wid = threadIdx.x >> 5, lane = threadIdx.x & 31;
    const float* xb = g_x + (long)b * SEQ * DMODEL;

    float a0[4] = {0, 0, 0, 0}, a1[4] = {0, 0, 0, 0};
    for (int i = 0; i < 5; i++) {
        const int t = ch * 40 + i * 8 + wid;
        const float4* xr = (const float4*)(xb + (long)t * DMODEL);
        float4 v0 = xr[lane];
        float4 v1 = xr[lane + 32];
        float s1 = v0.x + v0.y + v0.z + v0.w + v1.x + v1.y + v1.z + v1.w;
        float s2 = v0.x * v0.x + v0.y * v0.y + v0.z * v0.z + v0.w * v0.w
                 + v1.x * v1.x + v1.y * v1.y + v1.z * v1.z + v1.w * v1.w;
#pragma unroll
        for (int o = 16; o > 0; o >>= 1) {
            s1 += __shfl_xor_sync(0xffffffffu, s1, o);
            s2 += __shfl_xor_sync(0xffffffffu, s2, o);
        }
        const float mu  = s1 * (1.0f / 256.0f);
        const float var = s2 * (1.0f / 256.0f) - mu * mu;
        const float inv = rsqrtf(var + 1e-5f);
        a0[0] += (v0.x - mu) * inv; a0[1] += (v0.y - mu) * inv;
        a0[2] += (v0.z - mu) * inv; a0[3] += (v0.w - mu) * inv;
        a1[0] += (v1.x - mu) * inv; a1[1] += (v1.y - mu) * inv;
        a1[2] += (v1.z - mu) * inv; a1[3] += (v1.w - mu) * inv;
    }
    __shared__ float red[8][DMODEL];
    float* rw = red[wid];
    *(float4*)&rw[lane * 4]       = *(float4*)a0;
    *(float4*)&rw[128 + lane * 4] = *(float4*)a1;
    __syncthreads();
    const int tid = threadIdx.x;
    if (tid < 64) {
        const int dbase = tid * 4;
        float4 s = make_float4(0, 0, 0, 0);
#pragma unroll
        for (int ww = 0; ww < 8; ww++) {
            float4 v = *(float4*)&red[ww][dbase];
            s.x += v.x; s.y += v.y; s.z += v.z; s.w += v.w;
        }
        *(float4*)&g_part[((long)b * 25 + ch) * DMODEL + dbase] = s;
    }
}

// =====================================================================
// Kernel 5b: deterministic reduce of 25 partials + scale/bias + /SEQ.
// =====================================================================
__global__ __launch_bounds__(256) void k_final_sum(const float* __restrict__ sc,
                                                   const float* __restrict__ bi) {
    const int b = blockIdx.x, tid = threadIdx.x;
    float s = 0.0f;
#pragma unroll 5
    for (int ch = 0; ch < 25; ch++) s += g_part[((long)b * 25 + ch) * DMODEL + tid];
    g_emb[b * DMODEL + tid] = s * (1.0f / (float)SEQ) * sc[tid] + bi[tid];
}

// =====================================================================
// Kernel 6: classification head. grid 32, block 128.
// =====================================================================
__global__ __launch_bounds__(128) void k_head(const float* __restrict__ w1,
                                              const float* __restrict__ b1,
                                              const float* __restrict__ w2,
                                              const float* __restrict__ b2,
                                              float* __restrict__ out) {
    const int b = blockIdx.x, tid = threadIdx.x;
    __shared__ float es[DMODEL];
    __shared__ float h1s[128];
    es[tid]       = g_emb[b * DMODEL + tid];
    es[tid + 128] = g_emb[b * DMODEL + tid + 128];
    __syncthreads();
    float a = b1[tid];
#pragma unroll 8
    for (int dmi = 0; dmi < DMODEL; dmi++) a += es[dmi] * w1[dmi * 128 + tid];
    h1s[tid] = gelu_exact(a);
    __syncthreads();
    if (tid < 8) {
        float o = b2[tid];
#pragma unroll 8
        for (int j = 0; j < 128; j++) o += h1s[j] * w2[j * 8 + tid];
        out[b * 8 + tid] = o;
    }
}

// =====================================================================
// launch
// =====================================================================
extern "C" void kernel_launch(void* const* d_in, const int* in_sizes, int n_in,
                              void* d_out, int out_size) {
    const float* waveform = (const float*)d_in[0];
    const float* conv_w   = (const float*)d_in[1];
    const float* pos_emb  = (const float*)d_in[2];
    const float* ln_scale = (const float*)d_in[3];
    const float* ln_bias  = (const float*)d_in[4];
    const float* w_ih     = (const float*)d_in[5];
    const float* w_hh     = (const float*)d_in[6];
    const float* b_ih     = (const float*)d_in[7];
    const float* b_hh     = (const float*)d_in[8];
    const float* fnorm_s  = (const float*)d_in[9];
    const float* fnorm_b  = (const float*)d_in[10];
    const float* head_w1  = (const float*)d_in[11];
    const float* head_b1  = (const float*)d_in[12];
    const float* head_w2  = (const float*)d_in[13];
    const float* head_b2  = (const float*)d_in[14];
    float* out = (float*)d_out;

    k_conv<<<500, 256>>>(waveform, conv_w, pos_emb);

    for (int lyr = 0; lyr < NLAYERS; lyr++) {
        k_ln<<<4000, 256>>>(ln_scale + lyr * DMODEL, ln_bias + lyr * DMODEL);
        dim3 gg(250, 6);
        k_gemm_xp<<<gg, 256>>>(w_ih + (long)lyr * G3 * DMODEL, b_ih + lyr * G3);
        dim3 gr(4, BATCH);
        k_gru<<<gr, 384>>>(w_hh + (long)lyr * G3 * DMODEL, b_hh + lyr * G3);
    }

    dim3 gf(25, BATCH);
    k_final_part<<<gf, 256>>>();
    k_final_sum<<<BATCH, 256>>>(fnorm_s, fnorm_b);
    k_head<<<BATCH, 128>>>(head_w1, head_b1, head_w2, head_b2, out);
}